// round 9
// baseline (speedup 1.0000x reference)
#include <cuda_runtime.h>
#include <cuda_fp16.h>
#include <cstdint>

#define O_N   50000
#define T_N   200000
#define DIN   128
#define HID   512
#define DOUT  128

// ---------------- device scratch (allocation-free rule) -----------------------
__device__ __half  g_objh [(size_t)O_N * DIN];   // obj  fp16
__device__ __half  g_predh[(size_t)T_N * DIN];   // pred fp16
__device__ __half  g_h    [(size_t)T_N * 512];   // [T, 512] fp16
__device__ float   g_pool [(size_t)O_N * HID];   // fp32 accum
__device__ __half  g_pool16[(size_t)O_N * 512];  // pooled fp16
__device__ __half  g_h2   [(size_t)O_N * 512];   // [O, 512] fp16
__device__ float   g_cnt  [O_N];
__device__ __half  g_bt1[(size_t)512  * 384];    // [N,K] fp16 (W1a^T)
__device__ __half  g_bt2[(size_t)1152 * 512];    // [N,K] fp16 (W1b^T)
__device__ __half  g_bt3[(size_t)512  * 512];    // [N,K] fp16 (W2a^T)
__device__ __half  g_bt4[(size_t)128  * 512];    // [N,K] fp16 (W2b^T)

// ---------------- PTX helpers -------------------------------------------------
__device__ __forceinline__ uint32_t smem_u32(const void* p) {
    uint32_t a;
    asm("{ .reg .u64 t; cvta.to.shared.u64 t, %1; cvt.u32.u64 %0, t; }" : "=r"(a) : "l"(p));
    return a;
}
__device__ __forceinline__ void cp_async16(uint32_t dst, const void* src, int sz) {
    asm volatile("cp.async.cg.shared.global [%0], [%1], 16, %2;"
                 :: "r"(dst), "l"(src), "r"(sz));
}
__device__ __forceinline__ void ldm_x4(uint32_t& r0, uint32_t& r1, uint32_t& r2,
                                       uint32_t& r3, uint32_t addr) {
    asm volatile("ldmatrix.sync.aligned.m8n8.x4.shared.b16 {%0,%1,%2,%3}, [%4];"
                 : "=r"(r0), "=r"(r1), "=r"(r2), "=r"(r3) : "r"(addr));
}
__device__ __forceinline__ void mma_f16(float* c, const uint32_t* a, const uint32_t* b) {
    asm volatile("mma.sync.aligned.m16n8k16.row.col.f32.f16.f16.f32 "
                 "{%0,%1,%2,%3}, {%4,%5,%6,%7}, {%8,%9}, {%0,%1,%2,%3};"
                 : "+f"(c[0]), "+f"(c[1]), "+f"(c[2]), "+f"(c[3])
                 : "r"(a[0]), "r"(a[1]), "r"(a[2]), "r"(a[3]), "r"(b[0]), "r"(b[1]));
}
__device__ __forceinline__ void red_add4(float* p, float a, float b, float c, float d) {
    asm volatile("red.global.add.v4.f32 [%0], {%1,%2,%3,%4};"
                 :: "l"(p), "f"(a), "f"(b), "f"(c), "f"(d) : "memory");
}

// ---------------- prep 1: zero pooled/cnt + obj/pred fp32->fp16 ----------------
// grid covers max(n4_pool, n4_pred) = 6.4M float4 slots
__global__ void prep1(const float4* __restrict__ obj, __half2* __restrict__ objh,
                      const float4* __restrict__ pred, __half2* __restrict__ predh,
                      float4* __restrict__ pool4, float* __restrict__ cnt) {
    int i = blockIdx.x * 256 + threadIdx.x;
    const int n4_obj  = O_N * DIN / 4;   // 1.6M
    const int n4_pred = T_N * DIN / 4;   // 6.4M
    const int n4_pool = O_N * HID / 4;   // 6.4M
    if (i < n4_pool) pool4[i] = make_float4(0.f, 0.f, 0.f, 0.f);
    if (i < O_N) cnt[i] = 0.f;
    if (i < n4_obj) {
        float4 v = obj[i];
        objh[2*i]   = __halves2half2(__float2half_rn(v.x), __float2half_rn(v.y));
        objh[2*i+1] = __halves2half2(__float2half_rn(v.z), __float2half_rn(v.w));
    }
    if (i < n4_pred) {
        float4 v = pred[i];
        predh[2*i]   = __halves2half2(__float2half_rn(v.x), __float2half_rn(v.y));
        predh[2*i+1] = __halves2half2(__float2half_rn(v.z), __float2half_rn(v.w));
    }
}

// ---------------- prep 2: all weight transposes + degree counts ----------------
// weight elems: bt1 196608 | bt2 589824 | bt3 262144 | bt4 65536  (cum 1114112)
__global__ void prep2(const float* __restrict__ W1a, const float* __restrict__ W1b,
                      const float* __restrict__ W2a, const float* __restrict__ W2b,
                      __half* __restrict__ bt1, __half* __restrict__ bt2,
                      __half* __restrict__ bt3, __half* __restrict__ bt4,
                      const int* __restrict__ edges, float* __restrict__ cnt) {
    int i = blockIdx.x * 256 + threadIdx.x;
    if (i < T_N) {
        atomicAdd(&cnt[edges[2*i]], 1.0f);
        atomicAdd(&cnt[edges[2*i + 1]], 1.0f);
    }
    const float* W; __half* Bt; int K, N, idx;
    if (i < 196608)       { W = W1a; Bt = bt1; K = 384; N = 512;  idx = i; }
    else if (i < 786432)  { W = W1b; Bt = bt2; K = 512; N = 1152; idx = i - 196608; }
    else if (i < 1048576) { W = W2a; Bt = bt3; K = 512; N = 512;  idx = i - 786432; }
    else if (i < 1114112) { W = W2b; Bt = bt4; K = 512; N = 128;  idx = i - 1048576; }
    else return;
    int n = idx / K, k = idx - n * K;
    Bt[idx] = __float2half_rn(W[(size_t)k * N + n]);
}

// pooled/counts -> plain fp16
__global__ void pscale_conv(const float4* __restrict__ pooled, const float* __restrict__ cnt,
                            __half* __restrict__ p16) {
    int i = blockIdx.x * 256 + threadIdx.x;
    if (i >= O_N * (HID / 4)) return;
    int r = i >> 7;
    float c = fminf(fmaxf(cnt[r], 1.0f), 50000.0f);
    float s = 1.0f / c;
    float4 v = pooled[i];
    __half* row = p16 + (size_t)r * 512;
    int c0 = (i & 127) * 4;
    *(__half2*)(row + c0)     = __halves2half2(__float2half_rn(v.x * s), __float2half_rn(v.y * s));
    *(__half2*)(row + c0 + 2) = __halves2half2(__float2half_rn(v.z * s), __float2half_rn(v.w * s));
}

// ---------------- shared GEMM machinery ---------------------------------------
#define BM 128
#define BN 128
#define BK 32
#define STG 3
#define STG_ELEM 8192          // (BM+BN)*BK 2-byte elements per stage

__device__ __forceinline__ void ld_tileB(const __half* __restrict__ Bt, uint32_t sb,
                                         int n0, int Kc, int kp, int tid) {
    #pragma unroll
    for (int t = 0; t < 4; t++) {
        int s = tid + t * 128;
        int row = s >> 2, ch = s & 3;
        uint32_t phys = row * 64 + ((ch ^ ((row >> 1) & 3)) << 4);
        cp_async16(sb + phys, Bt + (size_t)(n0 + row) * Kc + kp + ch * 8, 16);
    }
}

__device__ __forceinline__ void compute_chunk(uint32_t sa, uint32_t sb,
                                              int wm, int wn, int lane,
                                              float acc[4][8][4]) {
    #pragma unroll
    for (int ks = 0; ks < 2; ks++) {
        uint32_t a[4][4], b[8][2];
        #pragma unroll
        for (int mf = 0; mf < 4; mf++) {
            int row = wm + mf * 16 + (lane & 15);
            int ch  = ks * 2 + (lane >> 4);
            uint32_t addr = sa + row * 64 + ((ch ^ ((row >> 1) & 3)) << 4);
            ldm_x4(a[mf][0], a[mf][1], a[mf][2], a[mf][3], addr);
        }
        #pragma unroll
        for (int bi = 0; bi < 4; bi++) {
            int row = wn + bi * 16 + (lane & 15);
            int ch  = ks * 2 + (lane >> 4);
            uint32_t addr = sb + row * 64 + ((ch ^ ((row >> 1) & 3)) << 4);
            uint32_t r0, r1, r2, r3;
            ldm_x4(r0, r1, r2, r3, addr);
            b[bi*2+0][0] = r0; b[bi*2+0][1] = r2;
            b[bi*2+1][0] = r1; b[bi*2+1][1] = r3;
        }
        #pragma unroll
        for (int mf = 0; mf < 4; mf++)
            #pragma unroll
            for (int nf = 0; nf < 8; nf++)
                mma_f16(acc[mf][nf], a[mf], b[nf]);
    }
}

// ---------------- GEMM1 with fused edge gather --------------------------------
__global__ void __launch_bounds__(128, 3)
g1_gemm(const __half* __restrict__ objh, const __half* __restrict__ predh,
        const int* __restrict__ edges, const __half* __restrict__ Bt,
        const float* __restrict__ bias, __half* __restrict__ outh)
{
    extern __shared__ uint16_t smem[];
    const int tid  = threadIdx.x;
    const int wid  = tid >> 5;
    const int lane = tid & 31;
    const int m0   = blockIdx.y * BM;
    const int n0   = blockIdx.x * BN;
    const int wm   = (wid >> 1) * 64;
    const int wn   = (wid & 1) * 64;
    const int M    = T_N;
    const int Kc   = 384;

    int rs[4], ro[4], rv[4];
    #pragma unroll
    for (int t = 0; t < 4; t++) {
        int row = (tid + t * 128) >> 2;
        int gr  = m0 + row;
        rv[t] = (gr < M);
        rs[t] = rv[t] ? edges[2*gr]     : 0;
        ro[t] = rv[t] ? edges[2*gr + 1] : 0;
    }

    float acc[4][8][4];
    #pragma unroll
    for (int i = 0; i < 4; i++)
        #pragma unroll
        for (int j = 0; j < 8; j++)
            #pragma unroll
            for (int k = 0; k < 4; k++) acc[i][j][k] = 0.f;

    auto ld_tile = [&](int it, int buf) {
        const int kp  = it * BK;
        const int reg = kp >> 7;
        const int kc  = kp & 127;
        uint32_t sa = smem_u32(smem + buf * STG_ELEM);
        uint32_t sb = sa + 8192;
        #pragma unroll
        for (int t = 0; t < 4; t++) {
            int s = tid + t * 128;
            int row = s >> 2, ch = s & 3;
            uint32_t phys = row * 64 + ((ch ^ ((row >> 1) & 3)) << 4);
            int gr = m0 + row;
            int col = kc + ch * 8;
            const __half* src;
            if (reg == 0)      src = objh  + (size_t)rs[t] * DIN + col;
            else if (reg == 1) src = predh + (size_t)(rv[t] ? gr : 0) * DIN + col;
            else               src = objh  + (size_t)ro[t] * DIN + col;
            cp_async16(sa + phys, src, rv[t] ? 16 : 0);
        }
        ld_tileB(Bt, sb, n0, Kc, kp, tid);
    };

    const int NC = Kc / BK;   // 12
    #pragma unroll
    for (int i = 0; i < STG - 1; i++) {
        ld_tile(i, i);
        asm volatile("cp.async.commit_group;" ::: "memory");
    }
    for (int it = 0; it < NC; it++) {
        asm volatile("cp.async.wait_group 1;" ::: "memory");
        __syncthreads();
        if (it + STG - 1 < NC) ld_tile(it + STG - 1, (it + STG - 1) % STG);
        asm volatile("cp.async.commit_group;" ::: "memory");
        const int buf = it % STG;
        uint32_t sa = smem_u32(smem + buf * STG_ELEM);
        compute_chunk(sa, sa + 8192, wm, wn, lane, acc);
    }

    float bc[8][2];
    #pragma unroll
    for (int nf = 0; nf < 8; nf++) {
        float2 bv = __ldg((const float2*)&bias[n0 + wn + nf * 8 + (lane & 3) * 2]);
        bc[nf][0] = bv.x; bc[nf][1] = bv.y;
    }
    #pragma unroll
    for (int mf = 0; mf < 4; mf++)
        #pragma unroll
        for (int rh = 0; rh < 2; rh++) {
            const int gr = m0 + wm + mf * 16 + (lane >> 2) + rh * 8;
            if (gr >= M) continue;
            #pragma unroll
            for (int nf = 0; nf < 8; nf++) {
                const int col = n0 + wn + nf * 8 + (lane & 3) * 2;
                float v0 = fmaxf(acc[mf][nf][rh*2+0] + bc[nf][0], 0.f);
                float v1 = fmaxf(acc[mf][nf][rh*2+1] + bc[nf][1], 0.f);
                *(__half2*)&outh[(size_t)gr * HID + col] =
                    __halves2half2(__float2half_rn(v0), __float2half_rn(v1));
            }
        }
}

// ---------------- generic GEMM -------------------------------------------------
// EPI 0: fp32 store    EPI 2: GEMM2 router (v4 atomics)    EPI 3: fp16 store
template<int EPI>
__global__ void __launch_bounds__(128, 3)
mma_gemm(const __half* __restrict__ A, const __half* __restrict__ Bt,
         const float* __restrict__ bias, float* __restrict__ outf,
         __half* __restrict__ outh,
         int M, int strideA, int Kc, int ostride,
         const int* __restrict__ edges, float* __restrict__ pooled,
         float* __restrict__ newp)
{
    extern __shared__ uint16_t smem[];
    const int tid  = threadIdx.x;
    const int wid  = tid >> 5;
    const int lane = tid & 31;
    const int m0   = blockIdx.y * BM;
    const int n0   = blockIdx.x * BN;
    const int wm   = (wid >> 1) * 64;
    const int wn   = (wid & 1) * 64;

    float acc[4][8][4];
    #pragma unroll
    for (int i = 0; i < 4; i++)
        #pragma unroll
        for (int j = 0; j < 8; j++)
            #pragma unroll
            for (int k = 0; k < 4; k++) acc[i][j][k] = 0.f;

    auto ld_tile = [&](int it, int buf) {
        const int kp = it * BK;
        uint32_t sa = smem_u32(smem + buf * STG_ELEM);
        uint32_t sb = sa + 8192;
        #pragma unroll
        for (int t = 0; t < 4; t++) {
            int s = tid + t * 128;
            int row = s >> 2, ch = s & 3;
            uint32_t phys = row * 64 + ((ch ^ ((row >> 1) & 3)) << 4);
            int gr = m0 + row;
            cp_async16(sa + phys,
                       A + (size_t)(gr < M ? gr : 0) * strideA + kp + ch * 8,
                       gr < M ? 16 : 0);
        }
        ld_tileB(Bt, sb, n0, Kc, kp, tid);
    };

    const int NC = Kc / BK;
    #pragma unroll
    for (int i = 0; i < STG - 1; i++) {
        ld_tile(i, i);
        asm volatile("cp.async.commit_group;" ::: "memory");
    }
    for (int it = 0; it < NC; it++) {
        asm volatile("cp.async.wait_group 1;" ::: "memory");
        __syncthreads();
        if (it + STG - 1 < NC) ld_tile(it + STG - 1, (it + STG - 1) % STG);
        asm volatile("cp.async.commit_group;" ::: "memory");
        const int buf = it % STG;
        uint32_t sa = smem_u32(smem + buf * STG_ELEM);
        compute_chunk(sa, sa + 8192, wm, wn, lane, acc);
    }

    float bc[8][2];
    #pragma unroll
    for (int nf = 0; nf < 8; nf++) {
        float2 bv = __ldg((const float2*)&bias[n0 + wn + nf * 8 + (lane & 3) * 2]);
        bc[nf][0] = bv.x; bc[nf][1] = bv.y;
    }

    #pragma unroll
    for (int mf = 0; mf < 4; mf++)
        #pragma unroll
        for (int rh = 0; rh < 2; rh++) {
            const int gr = m0 + wm + mf * 16 + (lane >> 2) + rh * 8;
            if (gr >= M) continue;
            int es = 0, eo = 0;
            if (EPI == 2) { es = edges[2*gr]; eo = edges[2*gr + 1]; }
            #pragma unroll
            for (int nf = 0; nf < 8; nf++) {
                const int col = n0 + wn + nf * 8 + (lane & 3) * 2;
                float v0 = fmaxf(acc[mf][nf][rh*2+0] + bc[nf][0], 0.f);
                float v1 = fmaxf(acc[mf][nf][rh*2+1] + bc[nf][1], 0.f);
                if (EPI == 0) {
                    *(float2*)&outf[(size_t)gr * ostride + col] = make_float2(v0, v1);
                } else if (EPI == 3) {
                    *(__half2*)&outh[(size_t)gr * ostride + col] =
                        __halves2half2(__float2half_rn(v0), __float2half_rn(v1));
                } else {
                    // region uniform across warp (64-wide warp tile inside one
                    // 128-wide N tile; boundaries at 512/640 are 128-aligned)
                    if (col >= HID && col < HID + DOUT) {
                        *(float2*)&newp[(size_t)gr * DOUT + (col - HID)] = make_float2(v0, v1);
                    } else {
                        // lanes 2k/2k+1 hold adjacent col-pairs of the same row:
                        // merge via shfl, even lane issues one red.add.v4
                        float p0 = __shfl_xor_sync(0xffffffffu, v0, 1);
                        float p1 = __shfl_xor_sync(0xffffffffu, v1, 1);
                        if (!(lane & 1)) {
                            float* dst;
                            if (col < HID) dst = &pooled[(size_t)es * HID + col];
                            else           dst = &pooled[(size_t)eo * HID + (col - HID - DOUT)];
                            red_add4(dst, v0, v1, p0, p1);
                        }
                    }
                }
            }
        }
}

// ---------------- launch ------------------------------------------------------
// 7 launches; GEMM2 is launch #4 (the slot ncu's -s window lands on).
extern "C" void kernel_launch(void* const* d_in, const int* in_sizes, int n_in,
                              void* d_out, int out_size) {
    const float* obj  = (const float*)d_in[0];
    const float* pred = (const float*)d_in[1];
    const int*   edges= (const int*)  d_in[2];
    const float* W1a  = (const float*)d_in[3];
    const float* b1a  = (const float*)d_in[4];
    const float* W1b  = (const float*)d_in[5];
    const float* b1b  = (const float*)d_in[6];
    const float* W2a  = (const float*)d_in[7];
    const float* b2a  = (const float*)d_in[8];
    const float* W2b  = (const float*)d_in[9];
    const float* b2b  = (const float*)d_in[10];

    float* out     = (float*)d_out;
    float* new_obj = out;                       // [O, 128]
    float* new_p   = out + (size_t)O_N * DOUT;  // [T, 128]

    __half *objh, *predh, *h16, *p16, *h2, *bt1, *bt2, *bt3, *bt4;
    float *pooled, *cnt;
    cudaGetSymbolAddress((void**)&objh,   g_objh);
    cudaGetSymbolAddress((void**)&predh,  g_predh);
    cudaGetSymbolAddress((void**)&h16,    g_h);
    cudaGetSymbolAddress((void**)&pooled, g_pool);
    cudaGetSymbolAddress((void**)&p16,    g_pool16);
    cudaGetSymbolAddress((void**)&h2,     g_h2);
    cudaGetSymbolAddress((void**)&cnt,    g_cnt);
    cudaGetSymbolAddress((void**)&bt1,    g_bt1);
    cudaGetSymbolAddress((void**)&bt2,    g_bt2);
    cudaGetSymbolAddress((void**)&bt3,    g_bt3);
    cudaGetSymbolAddress((void**)&bt4,    g_bt4);

    const int SMEM = STG * STG_ELEM * 2;   // 49152 bytes
    cudaFuncSetAttribute((const void*)g1_gemm,     cudaFuncAttributeMaxDynamicSharedMemorySize, SMEM);
    cudaFuncSetAttribute((const void*)mma_gemm<0>, cudaFuncAttributeMaxDynamicSharedMemorySize, SMEM);
    cudaFuncSetAttribute((const void*)mma_gemm<2>, cudaFuncAttributeMaxDynamicSharedMemorySize, SMEM);
    cudaFuncSetAttribute((const void*)mma_gemm<3>, cudaFuncAttributeMaxDynamicSharedMemorySize, SMEM);

    const int MT_T = (T_N + 127) / 128;   // 1563
    const int MT_O = (O_N + 127) / 128;   // 391

    // 1: zero pooled/cnt + obj/pred fp16 converts (grid covers 6.4M slots)
    {   int span = T_N * DIN / 4;   // == O_N*HID/4 == 6.4M
        prep1<<<(span + 255) / 256, 256>>>(
            (const float4*)obj, (__half2*)objh,
            (const float4*)pred, (__half2*)predh,
            (float4*)pooled, cnt); }

    // 2: all weight transposes + degree counts
    prep2<<<(1114112 + 255) / 256, 256>>>(W1a, W1b, W2a, W2b,
                                          bt1, bt2, bt3, bt4, edges, cnt);

    // 3: GEMM1 (fused gather)
    g1_gemm<<<dim3(4, MT_T), 128, SMEM>>>(objh, predh, edges, bt1, b1a, h16);

    // 4: GEMM2 (scatter s/o + new_p)   <-- profiled slot
    mma_gemm<2><<<dim3(9, MT_T), 128, SMEM>>>(
        h16, bt2, b1b, nullptr, nullptr,
        T_N, 512, 512, 0, edges, pooled, new_p);

    // 5: pooled scale + fp16
    pscale_conv<<<(O_N * (HID / 4) + 255) / 256, 256>>>((const float4*)pooled, cnt, p16);

    // 6: GEMM3
    mma_gemm<3><<<dim3(4, MT_O), 128, SMEM>>>(
        p16, bt3, b2a, nullptr, h2,
        O_N, 512, 512, HID, nullptr, nullptr, nullptr);

    // 7: GEMM4
    mma_gemm<0><<<dim3(1, MT_O), 128, SMEM>>>(
        h2, bt4, b2b, new_obj, nullptr,
        O_N, 512, 512, DOUT, nullptr, nullptr, nullptr);
}

// round 10
// speedup vs baseline: 1.0154x; 1.0154x over previous
#include <cuda_runtime.h>
#include <cuda_fp16.h>
#include <cstdint>

#define O_N   50000
#define T_N   200000
#define DIN   128
#define HID   512
#define DOUT  128

// ---------------- device scratch (allocation-free rule) -----------------------
__device__ __half  g_objh [(size_t)O_N * DIN];   // obj  fp16
__device__ __half  g_predh[(size_t)T_N * DIN];   // pred fp16
__device__ __half  g_h    [(size_t)T_N * 512];   // [T, 512] fp16
__device__ float   g_pool [(size_t)O_N * HID];   // fp32 accum
__device__ __half  g_pool16[(size_t)O_N * 512];  // pooled fp16
__device__ __half  g_h2   [(size_t)O_N * 512];   // [O, 512] fp16
__device__ float   g_cnt  [O_N];
__device__ __half  g_bt1[(size_t)512  * 384];    // [N,K] fp16 (W1a^T)
__device__ __half  g_bt2[(size_t)1152 * 512];    // [N,K] fp16 (W1b^T)
__device__ __half  g_bt3[(size_t)512  * 512];    // [N,K] fp16 (W2a^T)
__device__ __half  g_bt4[(size_t)128  * 512];    // [N,K] fp16 (W2b^T)

// ---------------- PTX helpers -------------------------------------------------
__device__ __forceinline__ uint32_t smem_u32(const void* p) {
    uint32_t a;
    asm("{ .reg .u64 t; cvta.to.shared.u64 t, %1; cvt.u32.u64 %0, t; }" : "=r"(a) : "l"(p));
    return a;
}
__device__ __forceinline__ void cp_async16(uint32_t dst, const void* src, int sz) {
    asm volatile("cp.async.cg.shared.global [%0], [%1], 16, %2;"
                 :: "r"(dst), "l"(src), "r"(sz));
}
__device__ __forceinline__ void ldm_x4(uint32_t& r0, uint32_t& r1, uint32_t& r2,
                                       uint32_t& r3, uint32_t addr) {
    asm volatile("ldmatrix.sync.aligned.m8n8.x4.shared.b16 {%0,%1,%2,%3}, [%4];"
                 : "=r"(r0), "=r"(r1), "=r"(r2), "=r"(r3) : "r"(addr));
}
__device__ __forceinline__ void mma_f16(float* c, const uint32_t* a, const uint32_t* b) {
    asm volatile("mma.sync.aligned.m16n8k16.row.col.f32.f16.f16.f32 "
                 "{%0,%1,%2,%3}, {%4,%5,%6,%7}, {%8,%9}, {%0,%1,%2,%3};"
                 : "+f"(c[0]), "+f"(c[1]), "+f"(c[2]), "+f"(c[3])
                 : "r"(a[0]), "r"(a[1]), "r"(a[2]), "r"(a[3]), "r"(b[0]), "r"(b[1]));
}
__device__ __forceinline__ void red_add2(float* p, float a, float b) {
    asm volatile("red.global.add.v2.f32 [%0], {%1,%2};"
                 :: "l"(p), "f"(a), "f"(b) : "memory");
}

// ---------------- prep 1: zero pooled/cnt + obj/pred fp32->fp16 ----------------
__global__ void prep1(const float4* __restrict__ obj, __half2* __restrict__ objh,
                      const float4* __restrict__ pred, __half2* __restrict__ predh,
                      float4* __restrict__ pool4, float* __restrict__ cnt) {
    int i = blockIdx.x * 256 + threadIdx.x;
    const int n4_obj  = O_N * DIN / 4;   // 1.6M
    const int n4_pred = T_N * DIN / 4;   // 6.4M
    const int n4_pool = O_N * HID / 4;   // 6.4M
    if (i < n4_pool) pool4[i] = make_float4(0.f, 0.f, 0.f, 0.f);
    if (i < O_N) cnt[i] = 0.f;
    if (i < n4_obj) {
        float4 v = obj[i];
        objh[2*i]   = __halves2half2(__float2half_rn(v.x), __float2half_rn(v.y));
        objh[2*i+1] = __halves2half2(__float2half_rn(v.z), __float2half_rn(v.w));
    }
    if (i < n4_pred) {
        float4 v = pred[i];
        predh[2*i]   = __halves2half2(__float2half_rn(v.x), __float2half_rn(v.y));
        predh[2*i+1] = __halves2half2(__float2half_rn(v.z), __float2half_rn(v.w));
    }
}

// ---------------- prep 2: all weight transposes + degree counts ----------------
__global__ void prep2(const float* __restrict__ W1a, const float* __restrict__ W1b,
                      const float* __restrict__ W2a, const float* __restrict__ W2b,
                      __half* __restrict__ bt1, __half* __restrict__ bt2,
                      __half* __restrict__ bt3, __half* __restrict__ bt4,
                      const int* __restrict__ edges, float* __restrict__ cnt) {
    int i = blockIdx.x * 256 + threadIdx.x;
    if (i < T_N) {
        atomicAdd(&cnt[edges[2*i]], 1.0f);
        atomicAdd(&cnt[edges[2*i + 1]], 1.0f);
    }
    const float* W; __half* Bt; int K, N, idx;
    if (i < 196608)       { W = W1a; Bt = bt1; K = 384; N = 512;  idx = i; }
    else if (i < 786432)  { W = W1b; Bt = bt2; K = 512; N = 1152; idx = i - 196608; }
    else if (i < 1048576) { W = W2a; Bt = bt3; K = 512; N = 512;  idx = i - 786432; }
    else if (i < 1114112) { W = W2b; Bt = bt4; K = 512; N = 128;  idx = i - 1048576; }
    else return;
    int n = idx / K, k = idx - n * K;
    Bt[idx] = __float2half_rn(W[(size_t)k * N + n]);
}

// pooled/counts -> plain fp16
__global__ void pscale_conv(const float4* __restrict__ pooled, const float* __restrict__ cnt,
                            __half* __restrict__ p16) {
    int i = blockIdx.x * 256 + threadIdx.x;
    if (i >= O_N * (HID / 4)) return;
    int r = i >> 7;
    float c = fminf(fmaxf(cnt[r], 1.0f), 50000.0f);
    float s = 1.0f / c;
    float4 v = pooled[i];
    __half* row = p16 + (size_t)r * 512;
    int c0 = (i & 127) * 4;
    *(__half2*)(row + c0)     = __halves2half2(__float2half_rn(v.x * s), __float2half_rn(v.y * s));
    *(__half2*)(row + c0 + 2) = __halves2half2(__float2half_rn(v.z * s), __float2half_rn(v.w * s));
}

// ---------------- shared GEMM machinery ---------------------------------------
// CTA 128x128, 4 warps (64x64), BK=64, 2-stage pipeline, 128B-row swizzle.
#define BM 128
#define BN 128
#define BK 64
#define STG 2
#define STG_BYTES 32768        // (BM+BN)*BK*2 bytes per stage

__device__ __forceinline__ uint32_t phys128(int row, int ch) {
    return (uint32_t)(row * 128 + ((ch ^ (row & 7)) << 4));
}

__device__ __forceinline__ void ld_tileB(const __half* __restrict__ Bt, uint32_t sb,
                                         int n0, int Kc, int kp, int tid) {
    #pragma unroll
    for (int t = 0; t < 8; t++) {
        int s = tid + t * 128;
        int row = s >> 3, ch = s & 7;
        cp_async16(sb + phys128(row, ch), Bt + (size_t)(n0 + row) * Kc + kp + ch * 8, 16);
    }
}

__device__ __forceinline__ void compute_chunk(uint32_t sa, uint32_t sb,
                                              int wm, int wn, int lane,
                                              float acc[4][8][4]) {
    #pragma unroll
    for (int ks = 0; ks < 4; ks++) {
        uint32_t a[4][4], b[8][2];
        const int ch = ks * 2 + (lane >> 4);
        #pragma unroll
        for (int mf = 0; mf < 4; mf++) {
            int row = wm + mf * 16 + (lane & 15);
            ldm_x4(a[mf][0], a[mf][1], a[mf][2], a[mf][3], sa + phys128(row, ch));
        }
        #pragma unroll
        for (int bi = 0; bi < 4; bi++) {
            int row = wn + bi * 16 + (lane & 15);
            uint32_t r0, r1, r2, r3;
            ldm_x4(r0, r1, r2, r3, sb + phys128(row, ch));
            b[bi*2+0][0] = r0; b[bi*2+0][1] = r2;
            b[bi*2+1][0] = r1; b[bi*2+1][1] = r3;
        }
        #pragma unroll
        for (int mf = 0; mf < 4; mf++)
            #pragma unroll
            for (int nf = 0; nf < 8; nf++)
                mma_f16(acc[mf][nf], a[mf], b[nf]);
    }
}

// ---------------- GEMM1 with fused edge gather --------------------------------
// edges for this CTA's 128 rows cached in smem (after the two stages).
__global__ void __launch_bounds__(128, 3)
g1_gemm(const __half* __restrict__ objh, const __half* __restrict__ predh,
        const int* __restrict__ edges, const __half* __restrict__ Bt,
        const float* __restrict__ bias, __half* __restrict__ outh)
{
    extern __shared__ char smem[];
    const int tid  = threadIdx.x;
    const int wid  = tid >> 5;
    const int lane = tid & 31;
    const int m0   = blockIdx.y * BM;
    const int n0   = blockIdx.x * BN;
    const int wm   = (wid >> 1) * 64;
    const int wn   = (wid & 1) * 64;
    const int M    = T_N;
    const int Kc   = 384;

    int2* esm = (int2*)(smem + STG * STG_BYTES);   // [128] (s, o) pairs
    {
        int gr = m0 + tid;
        esm[tid] = (gr < M) ? *(const int2*)&edges[2*gr] : make_int2(0, 0);
    }
    __syncthreads();

    float acc[4][8][4];
    #pragma unroll
    for (int i = 0; i < 4; i++)
        #pragma unroll
        for (int j = 0; j < 8; j++)
            #pragma unroll
            for (int k = 0; k < 4; k++) acc[i][j][k] = 0.f;

    auto ld_tile = [&](int it, int buf) {
        const int kp  = it * BK;
        const int reg = kp >> 7;          // 0: obj[s], 1: pred, 2: obj[o]
        const int kc  = kp & 127;
        uint32_t sa = smem_u32(smem + buf * STG_BYTES);
        uint32_t sb = sa + 16384;
        #pragma unroll
        for (int t = 0; t < 8; t++) {
            int s = tid + t * 128;
            int row = s >> 3, ch = s & 7;
            int gr = m0 + row;
            bool v = gr < M;
            int col = kc + ch * 8;
            const __half* src;
            if (reg == 0)      src = objh  + (size_t)esm[row].x * DIN + col;
            else if (reg == 1) src = predh + (size_t)(v ? gr : 0) * DIN + col;
            else               src = objh  + (size_t)esm[row].y * DIN + col;
            cp_async16(sa + phys128(row, ch), src, v ? 16 : 0);
        }
        ld_tileB(Bt, sb, n0, Kc, kp, tid);
    };

    const int NC = Kc / BK;   // 6
    ld_tile(0, 0);
    asm volatile("cp.async.commit_group;" ::: "memory");
    for (int it = 0; it < NC; it++) {
        asm volatile("cp.async.wait_group 0;" ::: "memory");
        __syncthreads();
        if (it + 1 < NC) ld_tile(it + 1, (it + 1) & 1);
        asm volatile("cp.async.commit_group;" ::: "memory");
        uint32_t sa = smem_u32(smem + (it & 1) * STG_BYTES);
        compute_chunk(sa, sa + 16384, wm, wn, lane, acc);
    }

    float bc[8][2];
    #pragma unroll
    for (int nf = 0; nf < 8; nf++) {
        float2 bv = __ldg((const float2*)&bias[n0 + wn + nf * 8 + (lane & 3) * 2]);
        bc[nf][0] = bv.x; bc[nf][1] = bv.y;
    }
    #pragma unroll
    for (int mf = 0; mf < 4; mf++)
        #pragma unroll
        for (int rh = 0; rh < 2; rh++) {
            const int gr = m0 + wm + mf * 16 + (lane >> 2) + rh * 8;
            if (gr >= M) continue;
            #pragma unroll
            for (int nf = 0; nf < 8; nf++) {
                const int col = n0 + wn + nf * 8 + (lane & 3) * 2;
                float v0 = fmaxf(acc[mf][nf][rh*2+0] + bc[nf][0], 0.f);
                float v1 = fmaxf(acc[mf][nf][rh*2+1] + bc[nf][1], 0.f);
                *(__half2*)&outh[(size_t)gr * HID + col] =
                    __halves2half2(__float2half_rn(v0), __float2half_rn(v1));
            }
        }
}

// ---------------- generic GEMM -------------------------------------------------
// EPI 0: fp32 store    EPI 2: GEMM2 router    EPI 3: plain fp16 store
template<int EPI>
__global__ void __launch_bounds__(128, 3)
mma_gemm(const __half* __restrict__ A, const __half* __restrict__ Bt,
         const float* __restrict__ bias, float* __restrict__ outf,
         __half* __restrict__ outh,
         int M, int strideA, int Kc, int ostride,
         const int* __restrict__ edges, float* __restrict__ pooled,
         float* __restrict__ newp)
{
    extern __shared__ char smem[];
    const int tid  = threadIdx.x;
    const int wid  = tid >> 5;
    const int lane = tid & 31;
    const int m0   = blockIdx.y * BM;
    const int n0   = blockIdx.x * BN;
    const int wm   = (wid >> 1) * 64;
    const int wn   = (wid & 1) * 64;

    float acc[4][8][4];
    #pragma unroll
    for (int i = 0; i < 4; i++)
        #pragma unroll
        for (int j = 0; j < 8; j++)
            #pragma unroll
            for (int k = 0; k < 4; k++) acc[i][j][k] = 0.f;

    auto ld_tile = [&](int it, int buf) {
        const int kp = it * BK;
        uint32_t sa = smem_u32(smem + buf * STG_BYTES);
        uint32_t sb = sa + 16384;
        #pragma unroll
        for (int t = 0; t < 8; t++) {
            int s = tid + t * 128;
            int row = s >> 3, ch = s & 7;
            int gr = m0 + row;
            cp_async16(sa + phys128(row, ch),
                       A + (size_t)(gr < M ? gr : 0) * strideA + kp + ch * 8,
                       gr < M ? 16 : 0);
        }
        ld_tileB(Bt, sb, n0, Kc, kp, tid);
    };

    const int NC = Kc / BK;
    ld_tile(0, 0);
    asm volatile("cp.async.commit_group;" ::: "memory");
    for (int it = 0; it < NC; it++) {
        asm volatile("cp.async.wait_group 0;" ::: "memory");
        __syncthreads();
        if (it + 1 < NC) ld_tile(it + 1, (it + 1) & 1);
        asm volatile("cp.async.commit_group;" ::: "memory");
        uint32_t sa = smem_u32(smem + (it & 1) * STG_BYTES);
        compute_chunk(sa, sa + 16384, wm, wn, lane, acc);
    }

    float bc[8][2];
    #pragma unroll
    for (int nf = 0; nf < 8; nf++) {
        float2 bv = __ldg((const float2*)&bias[n0 + wn + nf * 8 + (lane & 3) * 2]);
        bc[nf][0] = bv.x; bc[nf][1] = bv.y;
    }

    #pragma unroll
    for (int mf = 0; mf < 4; mf++)
        #pragma unroll
        for (int rh = 0; rh < 2; rh++) {
            const int gr = m0 + wm + mf * 16 + (lane >> 2) + rh * 8;
            if (gr >= M) continue;
            int es = 0, eo = 0;
            if (EPI == 2) { es = edges[2*gr]; eo = edges[2*gr + 1]; }
            #pragma unroll
            for (int nf = 0; nf < 8; nf++) {
                const int col = n0 + wn + nf * 8 + (lane & 3) * 2;
                float v0 = fmaxf(acc[mf][nf][rh*2+0] + bc[nf][0], 0.f);
                float v1 = fmaxf(acc[mf][nf][rh*2+1] + bc[nf][1], 0.f);
                if (EPI == 0) {
                    *(float2*)&outf[(size_t)gr * ostride + col] = make_float2(v0, v1);
                } else if (EPI == 3) {
                    *(__half2*)&outh[(size_t)gr * ostride + col] =
                        __halves2half2(__float2half_rn(v0), __float2half_rn(v1));
                } else {
                    if (col < HID) {
                        red_add2(&pooled[(size_t)es * HID + col], v0, v1);
                    } else if (col < HID + DOUT) {
                        *(float2*)&newp[(size_t)gr * DOUT + (col - HID)] = make_float2(v0, v1);
                    } else {
                        red_add2(&pooled[(size_t)eo * HID + (col - HID - DOUT)], v0, v1);
                    }
                }
            }
        }
}

// ---------------- launch ------------------------------------------------------
// 7 launches; GEMM2 is launch #4 (the profiled slot).
extern "C" void kernel_launch(void* const* d_in, const int* in_sizes, int n_in,
                              void* d_out, int out_size) {
    const float* obj  = (const float*)d_in[0];
    const float* pred = (const float*)d_in[1];
    const int*   edges= (const int*)  d_in[2];
    const float* W1a  = (const float*)d_in[3];
    const float* b1a  = (const float*)d_in[4];
    const float* W1b  = (const float*)d_in[5];
    const float* b1b  = (const float*)d_in[6];
    const float* W2a  = (const float*)d_in[7];
    const float* b2a  = (const float*)d_in[8];
    const float* W2b  = (const float*)d_in[9];
    const float* b2b  = (const float*)d_in[10];

    float* out     = (float*)d_out;
    float* new_obj = out;                       // [O, 128]
    float* new_p   = out + (size_t)O_N * DOUT;  // [T, 128]

    __half *objh, *predh, *h16, *p16, *h2, *bt1, *bt2, *bt3, *bt4;
    float *pooled, *cnt;
    cudaGetSymbolAddress((void**)&objh,   g_objh);
    cudaGetSymbolAddress((void**)&predh,  g_predh);
    cudaGetSymbolAddress((void**)&h16,    g_h);
    cudaGetSymbolAddress((void**)&pooled, g_pool);
    cudaGetSymbolAddress((void**)&p16,    g_pool16);
    cudaGetSymbolAddress((void**)&h2,     g_h2);
    cudaGetSymbolAddress((void**)&cnt,    g_cnt);
    cudaGetSymbolAddress((void**)&bt1,    g_bt1);
    cudaGetSymbolAddress((void**)&bt2,    g_bt2);
    cudaGetSymbolAddress((void**)&bt3,    g_bt3);
    cudaGetSymbolAddress((void**)&bt4,    g_bt4);

    const int SMEM_G  = STG * STG_BYTES;          // 65536
    const int SMEM_G1 = SMEM_G + 128 * 8;         // + edge cache (1 KB)
    cudaFuncSetAttribute((const void*)g1_gemm,     cudaFuncAttributeMaxDynamicSharedMemorySize, SMEM_G1);
    cudaFuncSetAttribute((const void*)mma_gemm<0>, cudaFuncAttributeMaxDynamicSharedMemorySize, SMEM_G);
    cudaFuncSetAttribute((const void*)mma_gemm<2>, cudaFuncAttributeMaxDynamicSharedMemorySize, SMEM_G);
    cudaFuncSetAttribute((const void*)mma_gemm<3>, cudaFuncAttributeMaxDynamicSharedMemorySize, SMEM_G);

    const int MT_T = (T_N + 127) / 128;   // 1563
    const int MT_O = (O_N + 127) / 128;   // 391

    // 1: zero pooled/cnt + obj/pred fp16 converts
    {   int span = T_N * DIN / 4;   // 6.4M
        prep1<<<(span + 255) / 256, 256>>>(
            (const float4*)obj, (__half2*)objh,
            (const float4*)pred, (__half2*)predh,
            (float4*)pooled, cnt); }

    // 2: all weight transposes + degree counts
    prep2<<<(1114112 + 255) / 256, 256>>>(W1a, W1b, W2a, W2b,
                                          bt1, bt2, bt3, bt4, edges, cnt);

    // 3: GEMM1 (fused gather)
    g1_gemm<<<dim3(4, MT_T), 128, SMEM_G1>>>(objh, predh, edges, bt1, b1a, h16);

    // 4: GEMM2 (scatter s/o + new_p)   <-- profiled slot
    mma_gemm<2><<<dim3(9, MT_T), 128, SMEM_G>>>(
        h16, bt2, b1b, nullptr, nullptr,
        T_N, 512, 512, 0, edges, pooled, new_p);

    // 5: pooled scale + fp16
    pscale_conv<<<(O_N * (HID / 4) + 255) / 256, 256>>>((const float4*)pooled, cnt, p16);

    // 6: GEMM3
    mma_gemm<3><<<dim3(4, MT_O), 128, SMEM_G>>>(
        p16, bt3, b2a, nullptr, h2,
        O_N, 512, 512, HID, nullptr, nullptr, nullptr);

    // 7: GEMM4
    mma_gemm<0><<<dim3(1, MT_O), 128, SMEM_G>>>(
        h2, bt4, b2b, new_obj, nullptr,
        O_N, 512, 512, DOUT, nullptr, nullptr, nullptr);
}

// round 11
// speedup vs baseline: 1.1497x; 1.1323x over previous
#include <cuda_runtime.h>
#include <cuda_fp16.h>
#include <cstdint>

#define O_N   50000
#define T_N   200000
#define DIN   128
#define HID   512
#define DOUT  128

// padded row counts (one extra M-tile so GEMM loaders need no bounds checks)
#define T_PAD 200064
#define O_PAD 50048

// ---------------- device scratch (allocation-free rule) -----------------------
__device__ __half  g_objh [(size_t)O_N * DIN];    // obj fp16 (indexed, no pad needed)
__device__ __half  g_predh[(size_t)T_PAD * DIN];  // pred fp16 (padded)
__device__ __half  g_h    [(size_t)T_PAD * 512];  // [T, 512] fp16 (padded)
__device__ float   g_pool [(size_t)O_N * HID];    // fp32 accum
__device__ __half  g_pool16[(size_t)O_PAD * 512]; // pooled fp16 (padded)
__device__ __half  g_h2   [(size_t)O_PAD * 512];  // [O, 512] fp16 (padded)
__device__ float   g_cnt  [O_N];
__device__ __half  g_bt1[(size_t)512  * 384];     // [N,K] fp16 (W1a^T)
__device__ __half  g_bt2[(size_t)1152 * 512];     // [N,K] fp16 (W1b^T)
__device__ __half  g_bt3[(size_t)512  * 512];     // [N,K] fp16 (W2a^T)
__device__ __half  g_bt4[(size_t)128  * 512];     // [N,K] fp16 (W2b^T)

// ---------------- PTX helpers -------------------------------------------------
__device__ __forceinline__ uint32_t smem_u32(const void* p) {
    uint32_t a;
    asm("{ .reg .u64 t; cvta.to.shared.u64 t, %1; cvt.u32.u64 %0, t; }" : "=r"(a) : "l"(p));
    return a;
}
__device__ __forceinline__ void cp_async16(uint32_t dst, const void* src) {
    asm volatile("cp.async.cg.shared.global [%0], [%1], 16;"
                 :: "r"(dst), "l"(src));
}
__device__ __forceinline__ void ldm_x4(uint32_t& r0, uint32_t& r1, uint32_t& r2,
                                       uint32_t& r3, uint32_t addr) {
    asm volatile("ldmatrix.sync.aligned.m8n8.x4.shared.b16 {%0,%1,%2,%3}, [%4];"
                 : "=r"(r0), "=r"(r1), "=r"(r2), "=r"(r3) : "r"(addr));
}
__device__ __forceinline__ void mma_f16(float* c, const uint32_t* a, const uint32_t* b) {
    asm volatile("mma.sync.aligned.m16n8k16.row.col.f32.f16.f16.f32 "
                 "{%0,%1,%2,%3}, {%4,%5,%6,%7}, {%8,%9}, {%0,%1,%2,%3};"
                 : "+f"(c[0]), "+f"(c[1]), "+f"(c[2]), "+f"(c[3])
                 : "r"(a[0]), "r"(a[1]), "r"(a[2]), "r"(a[3]), "r"(b[0]), "r"(b[1]));
}
__device__ __forceinline__ void red_add2(float* p, float a, float b) {
    asm volatile("red.global.add.v2.f32 [%0], {%1,%2};"
                 :: "l"(p), "f"(a), "f"(b) : "memory");
}

// ---------------- prep 1: zero pooled/cnt + obj/pred fp32->fp16 ----------------
__global__ void prep1(const float4* __restrict__ obj, __half2* __restrict__ objh,
                      const float4* __restrict__ pred, __half2* __restrict__ predh,
                      float4* __restrict__ pool4, float* __restrict__ cnt) {
    int i = blockIdx.x * 256 + threadIdx.x;
    const int n4_obj  = O_N * DIN / 4;
    const int n4_pred = T_N * DIN / 4;
    const int n4_pool = O_N * HID / 4;
    if (i < n4_pool) pool4[i] = make_float4(0.f, 0.f, 0.f, 0.f);
    if (i < O_N) cnt[i] = 0.f;
    if (i < n4_obj) {
        float4 v = obj[i];
        objh[2*i]   = __halves2half2(__float2half_rn(v.x), __float2half_rn(v.y));
        objh[2*i+1] = __halves2half2(__float2half_rn(v.z), __float2half_rn(v.w));
    }
    if (i < n4_pred) {
        float4 v = pred[i];
        predh[2*i]   = __halves2half2(__float2half_rn(v.x), __float2half_rn(v.y));
        predh[2*i+1] = __halves2half2(__float2half_rn(v.z), __float2half_rn(v.w));
    }
}

// ---------------- prep 2: all weight transposes + degree counts ----------------
__global__ void prep2(const float* __restrict__ W1a, const float* __restrict__ W1b,
                      const float* __restrict__ W2a, const float* __restrict__ W2b,
                      __half* __restrict__ bt1, __half* __restrict__ bt2,
                      __half* __restrict__ bt3, __half* __restrict__ bt4,
                      const int* __restrict__ edges, float* __restrict__ cnt) {
    int i = blockIdx.x * 256 + threadIdx.x;
    if (i < T_N) {
        atomicAdd(&cnt[edges[2*i]], 1.0f);
        atomicAdd(&cnt[edges[2*i + 1]], 1.0f);
    }
    const float* W; __half* Bt; int K, N, idx;
    if (i < 196608)       { W = W1a; Bt = bt1; K = 384; N = 512;  idx = i; }
    else if (i < 786432)  { W = W1b; Bt = bt2; K = 512; N = 1152; idx = i - 196608; }
    else if (i < 1048576) { W = W2a; Bt = bt3; K = 512; N = 512;  idx = i - 786432; }
    else if (i < 1114112) { W = W2b; Bt = bt4; K = 512; N = 128;  idx = i - 1048576; }
    else return;
    int n = idx / K, k = idx - n * K;
    Bt[idx] = __float2half_rn(W[(size_t)k * N + n]);
}

// pooled/counts -> plain fp16
__global__ void pscale_conv(const float4* __restrict__ pooled, const float* __restrict__ cnt,
                            __half* __restrict__ p16) {
    int i = blockIdx.x * 256 + threadIdx.x;
    if (i >= O_N * (HID / 4)) return;
    int r = i >> 7;
    float c = fminf(fmaxf(cnt[r], 1.0f), 50000.0f);
    float s = 1.0f / c;
    float4 v = pooled[i];
    __half* row = p16 + (size_t)r * 512;
    int c0 = (i & 127) * 4;
    *(__half2*)(row + c0)     = __halves2half2(__float2half_rn(v.x * s), __float2half_rn(v.y * s));
    *(__half2*)(row + c0 + 2) = __halves2half2(__float2half_rn(v.z * s), __float2half_rn(v.w * s));
}

// ---------------- shared GEMM machinery ---------------------------------------
// CTA 128x128, 4 warps (64x64), BK=64, 2-stage pipeline, 128B-row swizzle.
// All swizzle/address math hoisted: per-ldmatrix address is ONE IADD3.
#define BM 128
#define BN 128
#define BK 64
#define STG 2
#define STG_BYTES 32768

// Precomputed address state (rowbases relative to stage base; xor offsets per ks)
struct AddrCtx {
    uint32_t rbA[4], rbB[4], xoff[4];
};
__device__ __forceinline__ void make_ctx(AddrCtx& cx, int wm, int wn, int lane) {
    #pragma unroll
    for (int mf = 0; mf < 4; mf++) cx.rbA[mf] = (uint32_t)((wm + mf * 16 + (lane & 15)) * 128);
    #pragma unroll
    for (int bi = 0; bi < 4; bi++) cx.rbB[bi] = (uint32_t)((wn + bi * 16 + (lane & 15)) * 128);
    #pragma unroll
    for (int ks = 0; ks < 4; ks++)
        cx.xoff[ks] = (uint32_t)((((ks * 2 + (lane >> 4)) ^ (lane & 7))) << 4);
}

__device__ __forceinline__ void compute_chunk(uint32_t sa, uint32_t sb,
                                              const AddrCtx& cx,
                                              float acc[4][8][4]) {
    #pragma unroll
    for (int ks = 0; ks < 4; ks++) {
        const uint32_t sax = sa + cx.xoff[ks];
        const uint32_t sbx = sb + cx.xoff[ks];
        uint32_t a[4][4], b[8][2];
        #pragma unroll
        for (int mf = 0; mf < 4; mf++)
            ldm_x4(a[mf][0], a[mf][1], a[mf][2], a[mf][3], sax + cx.rbA[mf]);
        #pragma unroll
        for (int bi = 0; bi < 4; bi++) {
            uint32_t r0, r1, r2, r3;
            ldm_x4(r0, r1, r2, r3, sbx + cx.rbB[bi]);
            b[bi*2+0][0] = r0; b[bi*2+0][1] = r2;
            b[bi*2+1][0] = r1; b[bi*2+1][1] = r3;
        }
        #pragma unroll
        for (int mf = 0; mf < 4; mf++)
            #pragma unroll
            for (int nf = 0; nf < 8; nf++)
                mma_f16(acc[mf][nf], a[mf], b[nf]);
    }
}

// ---------------- GEMM1 with fused edge gather --------------------------------
__global__ void __launch_bounds__(128, 3)
g1_gemm(const __half* __restrict__ objh, const __half* __restrict__ predh,
        const int* __restrict__ edges, const __half* __restrict__ Bt,
        const float* __restrict__ bias, __half* __restrict__ outh)
{
    extern __shared__ char smem[];
    const int tid  = threadIdx.x;
    const int wid  = tid >> 5;
    const int lane = tid & 31;
    const int m0   = blockIdx.y * BM;
    const int n0   = blockIdx.x * BN;
    const int wm   = (wid >> 1) * 64;
    const int wn   = (wid & 1) * 64;
    const int M    = T_N;
    const int Kc   = 384;
    const uint32_t sbase = smem_u32(smem);

    int2* esm = (int2*)(smem + STG * STG_BYTES);
    {
        int gr = m0 + tid;
        esm[tid] = (gr < M) ? *(const int2*)&edges[2*gr] : make_int2(0, 0);
    }
    __syncthreads();

    AddrCtx cx; make_ctx(cx, wm, wn, lane);
    // loader per-thread constants
    const int lrow = tid >> 3, lch = tid & 7;
    const uint32_t off0 = (uint32_t)(lrow * 128 + ((lch ^ (lrow & 7)) << 4));
    const __half* bBase = Bt + (size_t)(n0 + lrow) * Kc + lch * 8;

    float acc[4][8][4];
    #pragma unroll
    for (int i = 0; i < 4; i++)
        #pragma unroll
        for (int j = 0; j < 8; j++)
            #pragma unroll
            for (int k = 0; k < 4; k++) acc[i][j][k] = 0.f;

    auto ld_tile = [&](int it, int buf) {
        const int kp  = it * BK;
        const int reg = kp >> 7;          // 0: obj[s], 1: pred, 2: obj[o]
        const int kc  = (kp & 127) + lch * 8;
        uint32_t sa = sbase + buf * STG_BYTES;
        uint32_t sb = sa + 16384;
        #pragma unroll
        for (int t = 0; t < 8; t++) {
            int row = lrow + t * 16;
            const __half* src;
            if (reg == 0)      src = objh  + (size_t)esm[row].x * DIN + kc;
            else if (reg == 1) src = predh + (size_t)(m0 + row) * DIN + kc;
            else               src = objh  + (size_t)esm[row].y * DIN + kc;
            cp_async16(sa + off0 + t * 2048, src);
        }
        const __half* pb = bBase + kp;
        #pragma unroll
        for (int t = 0; t < 8; t++) {
            cp_async16(sb + off0 + t * 2048, pb);
            pb += 16 * Kc;
        }
    };

    const int NC = Kc / BK;   // 6
    ld_tile(0, 0);
    asm volatile("cp.async.commit_group;" ::: "memory");
    for (int it = 0; it < NC; it++) {
        asm volatile("cp.async.wait_group 0;" ::: "memory");
        __syncthreads();
        if (it + 1 < NC) ld_tile(it + 1, (it + 1) & 1);
        asm volatile("cp.async.commit_group;" ::: "memory");
        uint32_t sa = sbase + (it & 1) * STG_BYTES;
        compute_chunk(sa, sa + 16384, cx, acc);
    }

    float bc[8][2];
    #pragma unroll
    for (int nf = 0; nf < 8; nf++) {
        float2 bv = __ldg((const float2*)&bias[n0 + wn + nf * 8 + (lane & 3) * 2]);
        bc[nf][0] = bv.x; bc[nf][1] = bv.y;
    }
    #pragma unroll
    for (int mf = 0; mf < 4; mf++)
        #pragma unroll
        for (int rh = 0; rh < 2; rh++) {
            const int gr = m0 + wm + mf * 16 + (lane >> 2) + rh * 8;
            if (gr >= M) continue;
            #pragma unroll
            for (int nf = 0; nf < 8; nf++) {
                const int col = n0 + wn + nf * 8 + (lane & 3) * 2;
                float v0 = fmaxf(acc[mf][nf][rh*2+0] + bc[nf][0], 0.f);
                float v1 = fmaxf(acc[mf][nf][rh*2+1] + bc[nf][1], 0.f);
                *(__half2*)&outh[(size_t)gr * HID + col] =
                    __halves2half2(__float2half_rn(v0), __float2half_rn(v1));
            }
        }
}

// ---------------- generic GEMM -------------------------------------------------
// A must be padded so rows [M, gridM*128) are readable (garbage rows are
// discarded by the guarded epilogue; MMA is row-local so no contamination).
// EPI 0: fp32 store    EPI 2: GEMM2 router    EPI 3: plain fp16 store
template<int EPI>
__global__ void __launch_bounds__(128, 3)
mma_gemm(const __half* __restrict__ A, const __half* __restrict__ Bt,
         const float* __restrict__ bias, float* __restrict__ outf,
         __half* __restrict__ outh,
         int M, int strideA, int Kc, int ostride,
         const int* __restrict__ edges, float* __restrict__ pooled,
         float* __restrict__ newp)
{
    extern __shared__ char smem[];
    const int tid  = threadIdx.x;
    const int wid  = tid >> 5;
    const int lane = tid & 31;
    const int m0   = blockIdx.y * BM;
    const int n0   = blockIdx.x * BN;
    const int wm   = (wid >> 1) * 64;
    const int wn   = (wid & 1) * 64;
    const uint32_t sbase = smem_u32(smem);

    AddrCtx cx; make_ctx(cx, wm, wn, lane);
    const int lrow = tid >> 3, lch = tid & 7;
    const uint32_t off0 = (uint32_t)(lrow * 128 + ((lch ^ (lrow & 7)) << 4));
    const __half* aBase = A  + (size_t)(m0 + lrow) * strideA + lch * 8;
    const __half* bBase = Bt + (size_t)(n0 + lrow) * Kc      + lch * 8;

    float acc[4][8][4];
    #pragma unroll
    for (int i = 0; i < 4; i++)
        #pragma unroll
        for (int j = 0; j < 8; j++)
            #pragma unroll
            for (int k = 0; k < 4; k++) acc[i][j][k] = 0.f;

    auto ld_tile = [&](int it, int buf) {
        const int kp = it * BK;
        uint32_t sa = sbase + buf * STG_BYTES;
        uint32_t sb = sa + 16384;
        const __half* pa = aBase + kp;
        const __half* pb = bBase + kp;
        #pragma unroll
        for (int t = 0; t < 8; t++) {
            cp_async16(sa + off0 + t * 2048, pa);
            pa += 16 * strideA;
        }
        #pragma unroll
        for (int t = 0; t < 8; t++) {
            cp_async16(sb + off0 + t * 2048, pb);
            pb += 16 * Kc;
        }
    };

    const int NC = Kc / BK;
    ld_tile(0, 0);
    asm volatile("cp.async.commit_group;" ::: "memory");
    for (int it = 0; it < NC; it++) {
        asm volatile("cp.async.wait_group 0;" ::: "memory");
        __syncthreads();
        if (it + 1 < NC) ld_tile(it + 1, (it + 1) & 1);
        asm volatile("cp.async.commit_group;" ::: "memory");
        uint32_t sa = sbase + (it & 1) * STG_BYTES;
        compute_chunk(sa, sa + 16384, cx, acc);
    }

    float bc[8][2];
    #pragma unroll
    for (int nf = 0; nf < 8; nf++) {
        float2 bv = __ldg((const float2*)&bias[n0 + wn + nf * 8 + (lane & 3) * 2]);
        bc[nf][0] = bv.x; bc[nf][1] = bv.y;
    }

    #pragma unroll
    for (int mf = 0; mf < 4; mf++)
        #pragma unroll
        for (int rh = 0; rh < 2; rh++) {
            const int gr = m0 + wm + mf * 16 + (lane >> 2) + rh * 8;
            if (gr >= M) continue;
            int es = 0, eo = 0;
            if (EPI == 2) { es = edges[2*gr]; eo = edges[2*gr + 1]; }
            #pragma unroll
            for (int nf = 0; nf < 8; nf++) {
                const int col = n0 + wn + nf * 8 + (lane & 3) * 2;
                float v0 = fmaxf(acc[mf][nf][rh*2+0] + bc[nf][0], 0.f);
                float v1 = fmaxf(acc[mf][nf][rh*2+1] + bc[nf][1], 0.f);
                if (EPI == 0) {
                    *(float2*)&outf[(size_t)gr * ostride + col] = make_float2(v0, v1);
                } else if (EPI == 3) {
                    *(__half2*)&outh[(size_t)gr * ostride + col] =
                        __halves2half2(__float2half_rn(v0), __float2half_rn(v1));
                } else {
                    if (col < HID) {
                        red_add2(&pooled[(size_t)es * HID + col], v0, v1);
                    } else if (col < HID + DOUT) {
                        *(float2*)&newp[(size_t)gr * DOUT + (col - HID)] = make_float2(v0, v1);
                    } else {
                        red_add2(&pooled[(size_t)eo * HID + (col - HID - DOUT)], v0, v1);
                    }
                }
            }
        }
}

// ---------------- launch ------------------------------------------------------
// 7 launches; GEMM2 is launch #4 (the profiled slot).
extern "C" void kernel_launch(void* const* d_in, const int* in_sizes, int n_in,
                              void* d_out, int out_size) {
    const float* obj  = (const float*)d_in[0];
    const float* pred = (const float*)d_in[1];
    const int*   edges= (const int*)  d_in[2];
    const float* W1a  = (const float*)d_in[3];
    const float* b1a  = (const float*)d_in[4];
    const float* W1b  = (const float*)d_in[5];
    const float* b1b  = (const float*)d_in[6];
    const float* W2a  = (const float*)d_in[7];
    const float* b2a  = (const float*)d_in[8];
    const float* W2b  = (const float*)d_in[9];
    const float* b2b  = (const float*)d_in[10];

    float* out     = (float*)d_out;
    float* new_obj = out;                       // [O, 128]
    float* new_p   = out + (size_t)O_N * DOUT;  // [T, 128]

    __half *objh, *predh, *h16, *p16, *h2, *bt1, *bt2, *bt3, *bt4;
    float *pooled, *cnt;
    cudaGetSymbolAddress((void**)&objh,   g_objh);
    cudaGetSymbolAddress((void**)&predh,  g_predh);
    cudaGetSymbolAddress((void**)&h16,    g_h);
    cudaGetSymbolAddress((void**)&pooled, g_pool);
    cudaGetSymbolAddress((void**)&p16,    g_pool16);
    cudaGetSymbolAddress((void**)&h2,     g_h2);
    cudaGetSymbolAddress((void**)&cnt,    g_cnt);
    cudaGetSymbolAddress((void**)&bt1,    g_bt1);
    cudaGetSymbolAddress((void**)&bt2,    g_bt2);
    cudaGetSymbolAddress((void**)&bt3,    g_bt3);
    cudaGetSymbolAddress((void**)&bt4,    g_bt4);

    const int SMEM_G  = STG * STG_BYTES;          // 65536
    const int SMEM_G1 = SMEM_G + 128 * 8;         // + edge cache (1 KB)
    cudaFuncSetAttribute((const void*)g1_gemm,     cudaFuncAttributeMaxDynamicSharedMemorySize, SMEM_G1);
    cudaFuncSetAttribute((const void*)mma_gemm<0>, cudaFuncAttributeMaxDynamicSharedMemorySize, SMEM_G);
    cudaFuncSetAttribute((const void*)mma_gemm<2>, cudaFuncAttributeMaxDynamicSharedMemorySize, SMEM_G);
    cudaFuncSetAttribute((const void*)mma_gemm<3>, cudaFuncAttributeMaxDynamicSharedMemorySize, SMEM_G);

    const int MT_T = (T_N + 127) / 128;   // 1563
    const int MT_O = (O_N + 127) / 128;   // 391

    // 1: zero pooled/cnt + obj/pred fp16 converts
    {   int span = T_N * DIN / 4;   // 6.4M
        prep1<<<(span + 255) / 256, 256>>>(
            (const float4*)obj, (__half2*)objh,
            (const float4*)pred, (__half2*)predh,
            (float4*)pooled, cnt); }

    // 2: all weight transposes + degree counts
    prep2<<<(1114112 + 255) / 256, 256>>>(W1a, W1b, W2a, W2b,
                                          bt1, bt2, bt3, bt4, edges, cnt);

    // 3: GEMM1 (fused gather)
    g1_gemm<<<dim3(4, MT_T), 128, SMEM_G1>>>(objh, predh, edges, bt1, b1a, h16);

    // 4: GEMM2 (scatter s/o + new_p)   <-- profiled slot
    mma_gemm<2><<<dim3(9, MT_T), 128, SMEM_G>>>(
        h16, bt2, b1b, nullptr, nullptr,
        T_N, 512, 512, 0, edges, pooled, new_p);

    // 5: pooled scale + fp16
    pscale_conv<<<(O_N * (HID / 4) + 255) / 256, 256>>>((const float4*)pooled, cnt, p16);

    // 6: GEMM3
    mma_gemm<3><<<dim3(4, MT_O), 128, SMEM_G>>>(
        p16, bt3, b2a, nullptr, h2,
        O_N, 512, 512, HID, nullptr, nullptr, nullptr);

    // 7: GEMM4
    mma_gemm<0><<<dim3(1, MT_O), 128, SMEM_G>>>(
        h2, bt4, b2b, new_obj, nullptr,
        O_N, 512, 512, DOUT, nullptr, nullptr, nullptr);
}